// round 12
// baseline (speedup 1.0000x reference)
#include <cuda_runtime.h>
#include <cuda_fp16.h>
#include <math.h>
#include <stdint.h>

#define HDIM 512
#define NLAYER 3
#define BATCH 16384
#define LN_EPS 1e-5f
#define FF 2048
#define BH ((size_t)BATCH * HDIM)
#define BFF ((size_t)BATCH * FF)
#define HH ((size_t)HDIM * HDIM)

// ---------------------------------------------------------------------------
// Scratch (device globals)
// ---------------------------------------------------------------------------
__device__ __half h_src [2 * BATCH * HDIM];
__device__ __half h_tgt [2 * BATCH * HDIM];
__device__ __half h_x   [2 * BATCH * HDIM];
__device__ __half h_t   [2 * BATCH * HDIM];
__device__ __half h_attn[6 * BATCH * HDIM];
__device__ __half h_hh  [2ULL * BATCH * FF];
__device__ __half w_ip[2 * HDIM * HDIM];
__device__ __half w_wv[6 * HDIM * HDIM];
__device__ __half w_wvT[6 * HDIM * HDIM];
__device__ __half w_ao[6 * HDIM * HDIM];
__device__ __half w_combo[6 * HDIM * HDIM];
__device__ __half w_f1[6 * FF * HDIM];
__device__ __half w_f2[6 * HDIM * FF];
__device__ __half w_op[2 * HDIM * HDIM];
__device__ float d_bcombo[6 * HDIM];
__device__ float d_zeros[HDIM];            // zero-initialized
__device__ int   d_idx[2 * BATCH];
__device__ int   d_cnt[2];
__device__ float d_prior_h[2 * HDIM];
__device__ float d_prior  [2 * HDIM];

__device__ __forceinline__ float gelu_exact(float v) {
    return 0.5f * v * (1.0f + erff(v * 0.70710678118654752440f));
}

#define CP16(dst, src) \
    asm volatile("cp.async.cg.shared.global [%0], [%1], 16;\n" :: "r"(dst), "l"(src))

__device__ __forceinline__ void ldsm4(uint32_t& r0, uint32_t& r1, uint32_t& r2,
                                      uint32_t& r3, uint32_t addr) {
    asm volatile("ldmatrix.sync.aligned.m8n8.x4.shared.b16 {%0,%1,%2,%3}, [%4];"
                 : "=r"(r0), "=r"(r1), "=r"(r2), "=r"(r3) : "r"(addr));
}

__device__ __forceinline__ void mma_f16(float* c, const uint32_t* a, const uint32_t* b) {
    asm volatile(
        "mma.sync.aligned.m16n8k16.row.col.f32.f16.f16.f32 "
        "{%0,%1,%2,%3}, {%4,%5,%6,%7}, {%8,%9}, {%0,%1,%2,%3};\n"
        : "+f"(c[0]), "+f"(c[1]), "+f"(c[2]), "+f"(c[3])
        : "r"(a[0]), "r"(a[1]), "r"(a[2]), "r"(a[3]), "r"(b[0]), "r"(b[1]));
}

// ---------------------------------------------------------------------------
// Small kernels
// ---------------------------------------------------------------------------
__global__ void reset_k() { if (threadIdx.x < 2) d_cnt[threadIdx.x] = 0; }

__global__ void compact_k(const int* __restrict__ mt) {
    int i = blockIdx.x * 256 + threadIdx.x;
    if (i < BATCH) {
        int m = mt[i];
        if (m == 1)      d_idx[atomicAdd(&d_cnt[0], 1)] = i;
        else if (m == 2) d_idx[BATCH + atomicAdd(&d_cnt[1], 1)] = i;
    }
}

// 4 warps per block, one output per warp
__global__ void prior1_k(const float* __restrict__ emb, const float* __restrict__ w1,
                         const float* __restrict__ b1) {
    int j = blockIdx.x * 4 + (threadIdx.x >> 5);
    int lane = threadIdx.x & 31;
    const float* wr = w1 + (size_t)j * HDIM;
    float s = 0.f;
    for (int k = lane; k < HDIM; k += 32) s += emb[k] * wr[k];
#pragma unroll
    for (int o = 16; o; o >>= 1) s += __shfl_xor_sync(0xffffffffu, s, o);
    if (lane == 0) d_prior_h[j] = gelu_exact(s + b1[j]);
}

__global__ void prior2_k(const float* __restrict__ w2, const float* __restrict__ b2) {
    int j = blockIdx.x * 4 + (threadIdx.x >> 5);
    int lane = threadIdx.x & 31;
    const float* wr = w2 + (size_t)j * (2 * HDIM);
    float s = 0.f;
    for (int k = lane; k < 2 * HDIM; k += 32) s += d_prior_h[k] * wr[k];
#pragma unroll
    for (int o = 16; o; o >>= 1) s += __shfl_xor_sync(0xffffffffu, s, o);
    if (lane == 0) d_prior[j] = s + b2[j];
}

__global__ void base_k(const float* __restrict__ img, const float* __restrict__ txt,
                       const int* __restrict__ mt, float* __restrict__ out) {
    int i = blockIdx.x * 256 + threadIdx.x;
    const int TOT = BATCH * HDIM / 4;
    if (i >= TOT) return;
    int b = i >> 7, h4 = i & 127, m = mt[b];
    float4 iv = reinterpret_cast<const float4*>(img)[i];
    float4 tv = reinterpret_cast<const float4*>(txt)[i];
    if (m == 3) {
        iv = reinterpret_cast<const float4*>(d_prior)[h4];
        tv = reinterpret_cast<const float4*>(d_prior + HDIM)[h4];
    }
    reinterpret_cast<float4*>(out)[i]       = iv;
    reinterpret_cast<float4*>(out)[TOT + i] = tv;
}

// one launch converting all plain-layout weights
__global__ void cvt_all_k(const float* __restrict__ ipw, const float* __restrict__ aow,
                          const float* __restrict__ f1w, const float* __restrict__ f2w,
                          const float* __restrict__ opw) {
    const int N_IP = (int)(2 * HH / 4);            // 131072
    const int N_AO = (int)(6 * HH / 4);            // 393216
    const int N_FF = (int)(6ULL * FF * HDIM / 4);  // 1572864
    int i = blockIdx.x * 256 + threadIdx.x;
    const float* s; __half* d; int li;
    if (i < N_IP)                          { s = ipw; d = w_ip; li = i; }
    else if ((i -= N_IP) < N_AO)           { s = aow; d = w_ao; li = i; }
    else if ((i -= N_AO) < N_FF)           { s = f1w; d = w_f1; li = i; }
    else if ((i -= N_FF) < N_FF)           { s = f2w; d = w_f2; li = i; }
    else if ((i -= N_FF) < N_IP)           { s = opw; d = w_op; li = i; }
    else return;
    float4 v = reinterpret_cast<const float4*>(s)[li];
    reinterpret_cast<__half2*>(d)[2 * li + 0] = __floats2half2_rn(v.x, v.y);
    reinterpret_cast<__half2*>(d)[2 * li + 1] = __floats2half2_rn(v.z, v.w);
}

__global__ void cvt_wv_k(const float* __restrict__ qkvw) {
    int i = blockIdx.x * 256 + threadIdx.x;
    const int N4 = 6 * HDIM * HDIM / 4;
    if (i >= N4) return;
    size_t e = (size_t)i * 4;
    size_t blk = e / HH, rem = e % HH;
    const float4 v = *reinterpret_cast<const float4*>(qkvw + blk * 3 * HH + 2 * HH + rem);
    reinterpret_cast<__half2*>(w_wv)[2 * i + 0] = __floats2half2_rn(v.x, v.y);
    reinterpret_cast<__half2*>(w_wv)[2 * i + 1] = __floats2half2_rn(v.z, v.w);
}

// transpose w_wv[z][o][i] -> w_wvT[z][i][o]
__global__ void transp_k() {
    __shared__ __half tile[32][33];
    int z  = blockIdx.z;
    int o0 = blockIdx.x * 32;
    int i0 = blockIdx.y * 32;
    const __half* src = w_wv + (size_t)z * HH;
    __half* dst = w_wvT + (size_t)z * HH;
    int tx = threadIdx.x, ty0 = threadIdx.y;      // 32 x 8
#pragma unroll
    for (int dy = 0; dy < 32; dy += 8)
        tile[ty0 + dy][tx] = src[(size_t)(o0 + ty0 + dy) * HDIM + i0 + tx];
    __syncthreads();
#pragma unroll
    for (int dy = 0; dy < 32; dy += 8)
        dst[(size_t)(i0 + ty0 + dy) * HDIM + o0 + tx] = tile[tx][ty0 + dy];
}

// b_combo[z][n] = sum_o ao[z][n][o] * bv[z][o] + ao_b[z][n]   (fp32)
__global__ void bcombo_k(const float* __restrict__ aow, const float* __restrict__ qkvb,
                         const float* __restrict__ aob) {
    int z = blockIdx.x >> 9;
    int n = blockIdx.x & 511;
    int lane = threadIdx.x;
    const float* ar = aow + ((size_t)z * HDIM + n) * HDIM;
    const float* bv = qkvb + (size_t)z * 3 * HDIM + 2 * HDIM;
    float s = 0.f;
    for (int o = lane; o < HDIM; o += 32) s += ar[o] * bv[o];
#pragma unroll
    for (int o = 16; o; o >>= 1) s += __shfl_xor_sync(0xffffffffu, s, o);
    if (lane == 0) d_bcombo[z * HDIM + n] = s + aob[(size_t)z * HDIM + n];
}

__global__ void gather_k(const float* __restrict__ img, const float* __restrict__ txt) {
    int z = blockIdx.y;
    int i = blockIdx.x * 256 + threadIdx.x;
    int r = i >> 7;
    if (r >= d_cnt[z]) return;
    int h4 = i & 127;
    int sr = d_idx[z * BATCH + r];
    const float* S = (z == 0) ? img : txt;
    const float* T = (z == 0) ? txt : img;
    float4 sv = reinterpret_cast<const float4*>(S)[sr * 128 + h4];
    float4 tv = reinterpret_cast<const float4*>(T)[sr * 128 + h4];
    size_t off2 = (size_t)z * BH / 2 + (size_t)i * 2;
    reinterpret_cast<__half2*>(h_src)[off2]     = __floats2half2_rn(sv.x, sv.y);
    reinterpret_cast<__half2*>(h_src)[off2 + 1] = __floats2half2_rn(sv.z, sv.w);
    reinterpret_cast<__half2*>(h_tgt)[off2]     = __floats2half2_rn(tv.x, tv.y);
    reinterpret_cast<__half2*>(h_tgt)[off2 + 1] = __floats2half2_rn(tv.z, tv.w);
}

// ---------------------------------------------------------------------------
// fp16 mma.sync GEMM: C[m,n] = sum_k A[m,k]*W[n,k] (+epilogue)
// BM=128, BN=128, BK=32, 3-stage cp.async, 256 threads, 2 CTAs/SM,
// 8 warps in 2x4 grid, warp tile 64x32. fixedM>0 overrides M=d_cnt[gi].
// ---------------------------------------------------------------------------
#define AST 40                            // smem row stride in halves (80 B)
#define STGS 3
#define A_TILE (128 * AST)                // halves
#define STG_H (2 * A_TILE)
#define SMEM_BYTES (STGS * STG_H * 2)     // 61440 B

template <int EPI>
__global__ __launch_bounds__(256, 2)
void gemm_h(const __half* __restrict__ A0, long long sA, int aByGi, int mDiv,
            const __half* __restrict__ W0, long long sW,
            const float* __restrict__ B0, long long sB,
            int K, int N,
            __half* __restrict__ C0, long long sC,
            const int* __restrict__ idx0,
            const float* __restrict__ feat0, const float* __restrict__ feat1,
            const float* __restrict__ rw0,
            float* __restrict__ out0, long long sOut, int fixedM) {
    const int z  = blockIdx.z;
    const int gi = z / mDiv;
    const int M  = fixedM > 0 ? fixedM : d_cnt[gi];
    const int m0 = blockIdx.x * 128;
    if (m0 >= M) return;
    const int n0 = blockIdx.y * 128;

    const __half* A    = A0 + (size_t)(aByGi ? gi : z) * sA;
    const __half* W    = W0 + (size_t)z * sW;
    const float*  bias = B0 + (size_t)z * sB;

    extern __shared__ __align__(16) __half smem[];
    // stage s: A at s*STG_H, B at s*STG_H + A_TILE

    const int tid  = threadIdx.x;
    const int warp = tid >> 5;
    const int lane = tid & 31;
    const int wM = (warp >> 2) * 64;       // 0 or 64
    const int wN = (warp & 3) * 32;        // 0,32,64,96

    // global->smem: row = tid>>1, 16-half chunk pair = tid&1
    const int grow = tid >> 1;
    const int gcol = (tid & 1) * 16;
    const __half* Ag = A + (size_t)(m0 + grow) * K + gcol;
    const __half* Wg = W + (size_t)(n0 + grow) * K + gcol;

    uint32_t aSt[STGS], bSt[STGS];
#pragma unroll
    for (int s = 0; s < STGS; s++) {
        aSt[s] = (uint32_t)__cvta_generic_to_shared(&smem[s * STG_H + grow * AST + gcol]);
        bSt[s] = (uint32_t)__cvta_generic_to_shared(&smem[s * STG_H + A_TILE + grow * AST + gcol]);
    }

    // ldmatrix lane mapping
    const int lr  = ((lane >> 3) & 1) * 8 + (lane & 7);
    const int lcB = (lane >> 4) * 16;      // bytes within k16
    uint32_t aLd[STGS], bLd[STGS];
#pragma unroll
    for (int s = 0; s < STGS; s++) {
        aLd[s] = (uint32_t)__cvta_generic_to_shared(&smem[s * STG_H + (wM + lr) * AST]) + lcB;
        bLd[s] = (uint32_t)__cvta_generic_to_shared(&smem[s * STG_H + A_TILE + (wN + lr) * AST]) + lcB;
    }

    float acc[4][4][4];
#pragma unroll
    for (int i = 0; i < 4; i++)
#pragma unroll
        for (int j = 0; j < 4; j++)
#pragma unroll
            for (int r = 0; r < 4; r++) acc[i][j][r] = 0.f;

    const int KT = K / 32;

#define LOAD_STG(kt_, s_)                                                      \
    {                                                                          \
        const __half* ag_ = Ag + (kt_) * 32;                                   \
        const __half* wg_ = Wg + (kt_) * 32;                                   \
        CP16(aSt[s_], ag_); CP16(aSt[s_] + 16, ag_ + 8);                       \
        CP16(bSt[s_], wg_); CP16(bSt[s_] + 16, wg_ + 8);                       \
    }

    // prologue: stages 0,1
    LOAD_STG(0, 0);
    asm volatile("cp.async.commit_group;\n");
    LOAD_STG(1, 1);
    asm volatile("cp.async.commit_group;\n");

    for (int kt = 0; kt < KT; kt++) {
        asm volatile("cp.async.wait_group 1;\n");
        __syncthreads();
        const int buf = kt % STGS;
        {
            const int pf = kt + 2;
            if (pf < KT) LOAD_STG(pf, pf % STGS);
            asm volatile("cp.async.commit_group;\n");
        }
#pragma unroll
        for (int kk = 0; kk < 2; kk++) {
            uint32_t af[4][4], bf[2][4];
#pragma unroll
            for (int mt = 0; mt < 4; mt++)
                ldsm4(af[mt][0], af[mt][1], af[mt][2], af[mt][3],
                      aLd[buf] + (mt * 16 * AST + kk * 16) * 2);
#pragma unroll
            for (int nt = 0; nt < 2; nt++)
                ldsm4(bf[nt][0], bf[nt][1], bf[nt][2], bf[nt][3],
                      bLd[buf] + (nt * 16 * AST + kk * 16) * 2);
#pragma unroll
            for (int mt = 0; mt < 4; mt++)
#pragma unroll
                for (int j = 0; j < 4; j++) {
                    uint32_t bb[2] = { bf[j >> 1][(j & 1)], bf[j >> 1][(j & 1) + 2] };
                    mma_f16(acc[mt][j], af[mt], bb);
                }
        }
    }

    // epilogue
    const int qr = lane >> 2, qc = lane & 3;
    float rw = 0.f;
    const int* idx = nullptr;
    const float* feat = nullptr;
    float* outz = nullptr;
    if (EPI == 2) {
        rw   = rw0[z];
        idx  = idx0 + (size_t)z * BATCH;
        feat = (z == 0) ? feat0 : feat1;
        outz = out0 + (long long)z * sOut;
    }
    __half* C = (EPI == 2) ? nullptr : (C0 + (size_t)z * sC);

#pragma unroll
    for (int mt = 0; mt < 4; mt++) {
        const int rm0 = m0 + wM + mt * 16 + qr;
#pragma unroll
        for (int r = 0; r < 2; r++) {
            const int gm = rm0 + r * 8;
            if (gm >= M) continue;
            int orow = 0;
            if (EPI == 2) orow = idx[gm];
#pragma unroll
            for (int j = 0; j < 4; j++) {
                const int gn = n0 + wN + j * 8 + qc * 2;
                float v0 = acc[mt][j][r * 2 + 0] + bias[gn];
                float v1 = acc[mt][j][r * 2 + 1] + bias[gn + 1];
                if (EPI == 0) {
                    reinterpret_cast<__half2*>(&C[(size_t)gm * N + gn])[0] =
                        __floats2half2_rn(v0, v1);
                } else if (EPI == 1) {
                    reinterpret_cast<__half2*>(&C[(size_t)gm * N + gn])[0] =
                        __floats2half2_rn(gelu_exact(v0), gelu_exact(v1));
                } else {
                    float2 t = *reinterpret_cast<const float2*>(&feat[(size_t)orow * HDIM + gn]);
                    *reinterpret_cast<float2*>(&outz[(size_t)orow * HDIM + gn]) =
                        make_float2(rw * t.x + (1.f - rw) * v0,
                                    rw * t.y + (1.f - rw) * v1);
                }
            }
        }
    }
#undef LOAD_STG
}

// ---------------------------------------------------------------------------
// Fused residual-add + LayerNorm (half in/out, fp32 math)
// ---------------------------------------------------------------------------
__global__ void ln_k(__half* __restrict__ x0, const __half* __restrict__ t0,
                     long long tsZ, const float* __restrict__ g0, long long gS,
                     const float* __restrict__ b0) {
    int z = blockIdx.y;
    int row = blockIdx.x;
    if (row >= d_cnt[z]) return;
    __half* x = x0 + (size_t)z * BH + (size_t)row * HDIM;
    const __half* t = t0 + (size_t)z * tsZ + (size_t)row * HDIM;
    const float* g  = g0 + (size_t)z * gS;
    const float* bb = b0 + (size_t)z * gS;
    int tid = threadIdx.x;
    uint2 ux = reinterpret_cast<const uint2*>(x)[tid];
    uint2 ut = reinterpret_cast<const uint2*>(t)[tid];
    float2 x0f = __half22float2(*reinterpret_cast<__half2*>(&ux.x));
    float2 x1f = __half22float2(*reinterpret_cast<__half2*>(&ux.y));
    float2 t0f = __half22float2(*reinterpret_cast<__half2*>(&ut.x));
    float2 t1f = __half22float2(*reinterpret_cast<__half2*>(&ut.y));
    float v0 = x0f.x + t0f.x, v1 = x0f.y + t0f.y;
    float v2 = x1f.x + t1f.x, v3 = x1f.y + t1f.y;
    float s = v0 + v1 + v2 + v3;
    float q = v0 * v0 + v1 * v1 + v2 * v2 + v3 * v3;
#pragma unroll
    for (int o = 16; o; o >>= 1) {
        s += __shfl_xor_sync(0xffffffffu, s, o);
        q += __shfl_xor_sync(0xffffffffu, q, o);
    }
    __shared__ float ss[4], sq[4];
    int w = tid >> 5, lane = tid & 31;
    if (lane == 0) { ss[w] = s; sq[w] = q; }
    __syncthreads();
    s = ss[0] + ss[1] + ss[2] + ss[3];
    q = sq[0] + sq[1] + sq[2] + sq[3];
    float mean = s * (1.f / HDIM);
    float var  = q * (1.f / HDIM) - mean * mean;
    float inv  = rsqrtf(var + LN_EPS);
    float4 gv = reinterpret_cast<const float4*>(g)[tid];
    float4 bv = reinterpret_cast<const float4*>(bb)[tid];
    uint2 uo;
    *reinterpret_cast<__half2*>(&uo.x) = __floats2half2_rn((v0 - mean) * inv * gv.x + bv.x,
                                                           (v1 - mean) * inv * gv.y + bv.y);
    *reinterpret_cast<__half2*>(&uo.y) = __floats2half2_rn((v2 - mean) * inv * gv.z + bv.z,
                                                           (v3 - mean) * inv * gv.w + bv.w);
    reinterpret_cast<uint2*>(x)[tid] = uo;
}

// ---------------------------------------------------------------------------
// Host launch
// ---------------------------------------------------------------------------
extern "C" void kernel_launch(void* const* d_in, const int* in_sizes, int n_in,
                              void* d_out, int out_size) {
    const float* img  = (const float*)d_in[0];
    const float* txt  = (const float*)d_in[1];
    const float* ipw  = (const float*)d_in[2];
    const float* ipb  = (const float*)d_in[3];
    const float* qkvw = (const float*)d_in[4];
    const float* qkvb = (const float*)d_in[5];
    const float* aow  = (const float*)d_in[6];
    const float* aob  = (const float*)d_in[7];
    const float* ln1g = (const float*)d_in[8];
    const float* ln1b = (const float*)d_in[9];
    const float* ln2g = (const float*)d_in[10];
    const float* ln2b = (const float*)d_in[11];
    const float* f1w  = (const float*)d_in[12];
    const float* f1b  = (const float*)d_in[13];
    const float* f2w  = (const float*)d_in[14];
    const float* f2b  = (const float*)d_in[15];
    const float* opw  = (const float*)d_in[16];
    const float* opb  = (const float*)d_in[17];
    const float* rw   = (const float*)d_in[18];
    const float* pw1  = (const float*)d_in[19];
    const float* pb1  = (const float*)d_in[20];
    const float* pw2  = (const float*)d_in[21];
    const float* pb2  = (const float*)d_in[22];
    const float* emb  = (const float*)d_in[23];
    const int*   mt   = (const int*)d_in[24];
    float* out = (float*)d_out;

    __half *pSrc, *pTgt, *pX, *pT, *pAttn, *pHH;
    __half *pWip, *pWao, *pWwvT, *pWcombo, *pWf1, *pWf2, *pWop;
    float *pBcombo, *pZeros;
    int *pIdx;
    cudaGetSymbolAddress((void**)&pSrc,    h_src);
    cudaGetSymbolAddress((void**)&pTgt,    h_tgt);
    cudaGetSymbolAddress((void**)&pX,      h_x);
    cudaGetSymbolAddress((void**)&pT,      h_t);
    cudaGetSymbolAddress((void**)&pAttn,   h_attn);
    cudaGetSymbolAddress((void**)&pHH,     h_hh);
    cudaGetSymbolAddress((void**)&pWip,    w_ip);
    cudaGetSymbolAddress((void**)&pWao,    w_ao);
    cudaGetSymbolAddress((void**)&pWwvT,   w_wvT);
    cudaGetSymbolAddress((void**)&pWcombo, w_combo);
    cudaGetSymbolAddress((void**)&pWf1,    w_f1);
    cudaGetSymbolAddress((void**)&pWf2,    w_f2);
    cudaGetSymbolAddress((void**)&pWop,    w_op);
    cudaGetSymbolAddress((void**)&pBcombo, d_bcombo);
    cudaGetSymbolAddress((void**)&pZeros,  d_zeros);
    cudaGetSymbolAddress((void**)&pIdx,    d_idx);

    cudaFuncSetAttribute(gemm_h<0>, cudaFuncAttributeMaxDynamicSharedMemorySize, SMEM_BYTES);
    cudaFuncSetAttribute(gemm_h<1>, cudaFuncAttributeMaxDynamicSharedMemorySize, SMEM_BYTES);
    cudaFuncSetAttribute(gemm_h<2>, cudaFuncAttributeMaxDynamicSharedMemorySize, SMEM_BYTES);

    dim3 g4 (BATCH / 128, HDIM / 128, 2);   // (128, 4, 2)
    dim3 g16(BATCH / 128, FF / 128,   2);   // (128, 16, 2)
    dim3 g6 (BATCH / 128, HDIM / 128, 6);   // (128, 4, 6)
    dim3 gC (HDIM / 128,  HDIM / 128, 6);   // (4, 4, 6) combo fold

    const int CVT_TOT = (int)(2 * (2 * HH / 4) + (6 * HH / 4) + 2 * (6ULL * FF * HDIM / 4));

    reset_k<<<1, 32>>>();
    compact_k<<<BATCH / 256, 256>>>(mt);
    cvt_wv_k<<<(int)(6 * HH / 4 + 255) / 256, 256>>>(qkvw);
    cvt_all_k<<<(CVT_TOT + 255) / 256, 256>>>(ipw, aow, f1w, f2w, opw);
    transp_k<<<dim3(16, 16, 6), dim3(32, 8)>>>();
    // combo[z][n][i] = sum_o ao[z][n][o] * wv[z][o][i]  (M=512 fixed)
    gemm_h<0><<<gC, 256, SMEM_BYTES>>>(pWao, (long long)HH, 0, 3,
                           pWwvT, (long long)HH, pZeros, 0,
                           HDIM, HDIM, pWcombo, (long long)HH,
                           nullptr, nullptr, nullptr, nullptr, nullptr, 0, HDIM);
    bcombo_k<<<6 * HDIM, 32>>>(aow, qkvb, aob);
    gather_k<<<dim3(BATCH * HDIM / 4 / 256, 2), 256>>>(img, txt);

    // attn[z] = tgt[gi] @ combo[z]^T + b_combo[z]
    gemm_h<0><<<g6, 256, SMEM_BYTES>>>(pTgt, (long long)BH, 1, 3,
                           pWcombo, (long long)HH, pBcombo, HDIM,
                           HDIM, HDIM, pAttn, (long long)BH,
                           nullptr, nullptr, nullptr, nullptr, nullptr, 0, 0);
    // x = src @ ipw^T + ipb
    gemm_h<0><<<g4, 256, SMEM_BYTES>>>(pSrc, (long long)BH, 1, 1,
                           pWip, (long long)HH, ipb, HDIM,
                           HDIM, HDIM, pX, (long long)BH,
                           nullptr, nullptr, nullptr, nullptr, nullptr, 0, 0);

    prior1_k<<<2 * HDIM / 4, 128>>>(emb, pw1, pb1);
    prior2_k<<<2 * HDIM / 4, 128>>>(pw2, pb2);
    base_k<<<BATCH * HDIM / 4 / 256, 256>>>(img, txt, mt, out);

    for (int l = 0; l < NLAYER; l++) {
        ln_k<<<dim3(BATCH, 2), 128>>>(pX, pAttn + (size_t)l * BH, (long long)(3 * BH),
                                      ln1g + l * HDIM, (long long)(NLAYER * HDIM),
                                      ln1b + l * HDIM);
        gemm_h<1><<<g16, 256, SMEM_BYTES>>>(pX, (long long)BH, 1, 1,
                                pWf1 + (size_t)l * FF * HDIM, (long long)(3ULL * FF * HDIM),
                                f1b + l * FF, (long long)(NLAYER * FF),
                                HDIM, FF, pHH, (long long)BFF,
                                nullptr, nullptr, nullptr, nullptr, nullptr, 0, 0);
        gemm_h<0><<<g4, 256, SMEM_BYTES>>>(pHH, (long long)BFF, 1, 1,
                               pWf2 + (size_t)l * HDIM * FF, (long long)(3ULL * HDIM * FF),
                               f2b + l * HDIM, (long long)(NLAYER * HDIM),
                               FF, HDIM, pT, (long long)BH,
                               nullptr, nullptr, nullptr, nullptr, nullptr, 0, 0);
        ln_k<<<dim3(BATCH, 2), 128>>>(pX, pT, (long long)BH,
                                      ln2g + l * HDIM, (long long)(NLAYER * HDIM),
                                      ln2b + l * HDIM);
    }

    // out[idx[m]] = rw*feat + (1-rw)*(x @ opw^T + opb)
    gemm_h<2><<<g4, 256, SMEM_BYTES>>>(pX, (long long)BH, 1, 1,
                           pWop, (long long)HH, opb, HDIM,
                           HDIM, HDIM, nullptr, 0,
                           pIdx, txt, img, rw,
                           out + BH, -(long long)BH, 0);
}

// round 13
// speedup vs baseline: 1.1338x; 1.1338x over previous
#include <cuda_runtime.h>
#include <cuda_fp16.h>
#include <math.h>
#include <stdint.h>

#define HDIM 512
#define NLAYER 3
#define BATCH 16384
#define LN_EPS 1e-5f
#define FF 2048
#define BH ((size_t)BATCH * HDIM)
#define BFF ((size_t)BATCH * FF)
#define HH ((size_t)HDIM * HDIM)

// ---------------------------------------------------------------------------
// Scratch (device globals)
// ---------------------------------------------------------------------------
__device__ __half h_src [2 * BATCH * HDIM];
__device__ __half h_tgt [2 * BATCH * HDIM];
__device__ __half h_x   [2 * BATCH * HDIM];
__device__ __half h_t   [2 * BATCH * HDIM];
__device__ __half h_attn[6 * BATCH * HDIM];
__device__ __half h_hh  [2ULL * BATCH * FF];
__device__ __half w_ip[2 * HDIM * HDIM];
__device__ __half w_wv[6 * HDIM * HDIM];
__device__ __half w_wvT[6 * HDIM * HDIM];
__device__ __half w_ao[6 * HDIM * HDIM];
__device__ __half w_combo[6 * HDIM * HDIM];
__device__ __half w_f1[6 * FF * HDIM];
__device__ __half w_f2[6 * HDIM * FF];
__device__ __half w_op[2 * HDIM * HDIM];
__device__ float d_bcombo[6 * HDIM];
__device__ float d_zeros[HDIM];            // zero-initialized
__device__ int   d_idx[2 * BATCH];
__device__ int   d_cnt[2];
__device__ float d_prior_h[2 * HDIM];
__device__ float d_prior  [2 * HDIM];

__device__ __forceinline__ float gelu_exact(float v) {
    return 0.5f * v * (1.0f + erff(v * 0.70710678118654752440f));
}

#define CP16(dst, src) \
    asm volatile("cp.async.cg.shared.global [%0], [%1], 16;\n" :: "r"(dst), "l"(src))

__device__ __forceinline__ void ldsm4(uint32_t& r0, uint32_t& r1, uint32_t& r2,
                                      uint32_t& r3, uint32_t addr) {
    asm volatile("ldmatrix.sync.aligned.m8n8.x4.shared.b16 {%0,%1,%2,%3}, [%4];"
                 : "=r"(r0), "=r"(r1), "=r"(r2), "=r"(r3) : "r"(addr));
}

__device__ __forceinline__ void mma_f16(float* c, const uint32_t* a, const uint32_t* b) {
    asm volatile(
        "mma.sync.aligned.m16n8k16.row.col.f32.f16.f16.f32 "
        "{%0,%1,%2,%3}, {%4,%5,%6,%7}, {%8,%9}, {%0,%1,%2,%3};\n"
        : "+f"(c[0]), "+f"(c[1]), "+f"(c[2]), "+f"(c[3])
        : "r"(a[0]), "r"(a[1]), "r"(a[2]), "r"(a[3]), "r"(b[0]), "r"(b[1]));
}

// ---------------------------------------------------------------------------
// Small kernels
// ---------------------------------------------------------------------------
__global__ void reset_k() { if (threadIdx.x < 2) d_cnt[threadIdx.x] = 0; }

__global__ void compact_k(const int* __restrict__ mt) {
    int i = blockIdx.x * 256 + threadIdx.x;
    if (i < BATCH) {
        int m = mt[i];
        if (m == 1)      d_idx[atomicAdd(&d_cnt[0], 1)] = i;
        else if (m == 2) d_idx[BATCH + atomicAdd(&d_cnt[1], 1)] = i;
    }
}

// 4 warps per block, one output per warp
__global__ void prior1_k(const float* __restrict__ emb, const float* __restrict__ w1,
                         const float* __restrict__ b1) {
    int j = blockIdx.x * 4 + (threadIdx.x >> 5);
    int lane = threadIdx.x & 31;
    const float* wr = w1 + (size_t)j * HDIM;
    float s = 0.f;
    for (int k = lane; k < HDIM; k += 32) s += emb[k] * wr[k];
#pragma unroll
    for (int o = 16; o; o >>= 1) s += __shfl_xor_sync(0xffffffffu, s, o);
    if (lane == 0) d_prior_h[j] = gelu_exact(s + b1[j]);
}

__global__ void prior2_k(const float* __restrict__ w2, const float* __restrict__ b2) {
    int j = blockIdx.x * 4 + (threadIdx.x >> 5);
    int lane = threadIdx.x & 31;
    const float* wr = w2 + (size_t)j * (2 * HDIM);
    float s = 0.f;
    for (int k = lane; k < 2 * HDIM; k += 32) s += d_prior_h[k] * wr[k];
#pragma unroll
    for (int o = 16; o; o >>= 1) s += __shfl_xor_sync(0xffffffffu, s, o);
    if (lane == 0) d_prior[j] = s + b2[j];
}

__global__ void base_k(const float* __restrict__ img, const float* __restrict__ txt,
                       const int* __restrict__ mt, float* __restrict__ out) {
    int i = blockIdx.x * 256 + threadIdx.x;
    const int TOT = BATCH * HDIM / 4;
    if (i >= TOT) return;
    int b = i >> 7, h4 = i & 127, m = mt[b];
    float4 iv = reinterpret_cast<const float4*>(img)[i];
    float4 tv = reinterpret_cast<const float4*>(txt)[i];
    if (m == 3) {
        iv = reinterpret_cast<const float4*>(d_prior)[h4];
        tv = reinterpret_cast<const float4*>(d_prior + HDIM)[h4];
    }
    reinterpret_cast<float4*>(out)[i]       = iv;
    reinterpret_cast<float4*>(out)[TOT + i] = tv;
}

// one launch converting all plain-layout weights
__global__ void cvt_all_k(const float* __restrict__ ipw, const float* __restrict__ aow,
                          const float* __restrict__ f1w, const float* __restrict__ f2w,
                          const float* __restrict__ opw) {
    const int N_IP = (int)(2 * HH / 4);            // 131072
    const int N_AO = (int)(6 * HH / 4);            // 393216
    const int N_FF = (int)(6ULL * FF * HDIM / 4);  // 1572864
    int i = blockIdx.x * 256 + threadIdx.x;
    const float* s; __half* d; int li;
    if (i < N_IP)                          { s = ipw; d = w_ip; li = i; }
    else if ((i -= N_IP) < N_AO)           { s = aow; d = w_ao; li = i; }
    else if ((i -= N_AO) < N_FF)           { s = f1w; d = w_f1; li = i; }
    else if ((i -= N_FF) < N_FF)           { s = f2w; d = w_f2; li = i; }
    else if ((i -= N_FF) < N_IP)           { s = opw; d = w_op; li = i; }
    else return;
    float4 v = reinterpret_cast<const float4*>(s)[li];
    reinterpret_cast<__half2*>(d)[2 * li + 0] = __floats2half2_rn(v.x, v.y);
    reinterpret_cast<__half2*>(d)[2 * li + 1] = __floats2half2_rn(v.z, v.w);
}

__global__ void cvt_wv_k(const float* __restrict__ qkvw) {
    int i = blockIdx.x * 256 + threadIdx.x;
    const int N4 = 6 * HDIM * HDIM / 4;
    if (i >= N4) return;
    size_t e = (size_t)i * 4;
    size_t blk = e / HH, rem = e % HH;
    const float4 v = *reinterpret_cast<const float4*>(qkvw + blk * 3 * HH + 2 * HH + rem);
    reinterpret_cast<__half2*>(w_wv)[2 * i + 0] = __floats2half2_rn(v.x, v.y);
    reinterpret_cast<__half2*>(w_wv)[2 * i + 1] = __floats2half2_rn(v.z, v.w);
}

// transpose w_wv[z][o][i] -> w_wvT[z][i][o]
__global__ void transp_k() {
    __shared__ __half tile[32][33];
    int z  = blockIdx.z;
    int o0 = blockIdx.x * 32;
    int i0 = blockIdx.y * 32;
    const __half* src = w_wv + (size_t)z * HH;
    __half* dst = w_wvT + (size_t)z * HH;
    int tx = threadIdx.x, ty0 = threadIdx.y;      // 32 x 8
#pragma unroll
    for (int dy = 0; dy < 32; dy += 8)
        tile[ty0 + dy][tx] = src[(size_t)(o0 + ty0 + dy) * HDIM + i0 + tx];
    __syncthreads();
#pragma unroll
    for (int dy = 0; dy < 32; dy += 8)
        dst[(size_t)(i0 + ty0 + dy) * HDIM + o0 + tx] = tile[tx][ty0 + dy];
}

// b_combo[z][n] = sum_o ao[z][n][o] * bv[z][o] + ao_b[z][n]   (fp32)
__global__ void bcombo_k(const float* __restrict__ aow, const float* __restrict__ qkvb,
                         const float* __restrict__ aob) {
    int z = blockIdx.x >> 9;
    int n = blockIdx.x & 511;
    int lane = threadIdx.x;
    const float* ar = aow + ((size_t)z * HDIM + n) * HDIM;
    const float* bv = qkvb + (size_t)z * 3 * HDIM + 2 * HDIM;
    float s = 0.f;
    for (int o = lane; o < HDIM; o += 32) s += ar[o] * bv[o];
#pragma unroll
    for (int o = 16; o; o >>= 1) s += __shfl_xor_sync(0xffffffffu, s, o);
    if (lane == 0) d_bcombo[z * HDIM + n] = s + aob[(size_t)z * HDIM + n];
}

__global__ void gather_k(const float* __restrict__ img, const float* __restrict__ txt) {
    int z = blockIdx.y;
    int i = blockIdx.x * 256 + threadIdx.x;
    int r = i >> 7;
    if (r >= d_cnt[z]) return;
    int h4 = i & 127;
    int sr = d_idx[z * BATCH + r];
    const float* S = (z == 0) ? img : txt;
    const float* T = (z == 0) ? txt : img;
    float4 sv = reinterpret_cast<const float4*>(S)[sr * 128 + h4];
    float4 tv = reinterpret_cast<const float4*>(T)[sr * 128 + h4];
    size_t off2 = (size_t)z * BH / 2 + (size_t)i * 2;
    reinterpret_cast<__half2*>(h_src)[off2]     = __floats2half2_rn(sv.x, sv.y);
    reinterpret_cast<__half2*>(h_src)[off2 + 1] = __floats2half2_rn(sv.z, sv.w);
    reinterpret_cast<__half2*>(h_tgt)[off2]     = __floats2half2_rn(tv.x, tv.y);
    reinterpret_cast<__half2*>(h_tgt)[off2 + 1] = __floats2half2_rn(tv.z, tv.w);
}

// ---------------------------------------------------------------------------
// fp16 mma.sync GEMM: C[m,n] = sum_k A[m,k]*W[n,k] (+epilogue)
// BM=128, BN=256, BK=32, 4-stage cp.async, 512 threads,
// 16 warps in 4x4 grid, warp tile 32x64. fixedM>0 overrides M=d_cnt[gi].
// (R11 configuration — verified fastest.)
// ---------------------------------------------------------------------------
#define AST 40                            // smem row stride in halves (80 B)
#define STGS 4
#define A_TILE (128 * AST)                // halves
#define B_TILE (256 * AST)
#define STG_H (A_TILE + B_TILE)
#define SMEM_BYTES (STGS * STG_H * 2)     // 122880 B

template <int EPI>
__global__ __launch_bounds__(512, 1)
void gemm_h(const __half* __restrict__ A0, long long sA, int aByGi, int mDiv,
            const __half* __restrict__ W0, long long sW,
            const float* __restrict__ B0, long long sB,
            int K, int N,
            __half* __restrict__ C0, long long sC,
            const int* __restrict__ idx0,
            const float* __restrict__ feat0, const float* __restrict__ feat1,
            const float* __restrict__ rw0,
            float* __restrict__ out0, long long sOut, int fixedM) {
    const int z  = blockIdx.z;
    const int gi = z / mDiv;
    const int M  = fixedM > 0 ? fixedM : d_cnt[gi];
    const int m0 = blockIdx.x * 128;
    if (m0 >= M) return;
    const int n0 = blockIdx.y * 256;

    const __half* A    = A0 + (size_t)(aByGi ? gi : z) * sA;
    const __half* W    = W0 + (size_t)z * sW;
    const float*  bias = B0 + (size_t)z * sB;

    extern __shared__ __align__(16) __half smem[];

    const int tid  = threadIdx.x;
    const int warp = tid >> 5;
    const int lane = tid & 31;
    const int wM = (warp >> 2) * 32;
    const int wN = (warp & 3) * 64;

    const int grow = tid >> 2;
    const int gcol = (tid & 3) * 8;
    const __half* Ag  = A + (size_t)(m0 + grow) * K + gcol;
    const __half* Wg  = W + (size_t)(n0 + grow) * K + gcol;
    const __half* Wg2 = Wg + (size_t)128 * K;

    uint32_t aSt[STGS], bSt[STGS], bSt2[STGS];
#pragma unroll
    for (int s = 0; s < STGS; s++) {
        aSt[s]  = (uint32_t)__cvta_generic_to_shared(&smem[s * STG_H + grow * AST + gcol]);
        bSt[s]  = (uint32_t)__cvta_generic_to_shared(&smem[s * STG_H + A_TILE + grow * AST + gcol]);
        bSt2[s] = bSt[s] + 128 * AST * 2;
    }

    const int lr  = ((lane >> 3) & 1) * 8 + (lane & 7);
    const int lcB = (lane >> 4) * 16;
    uint32_t aLd[STGS], bLd[STGS];
#pragma unroll
    for (int s = 0; s < STGS; s++) {
        aLd[s] = (uint32_t)__cvta_generic_to_shared(&smem[s * STG_H + (wM + lr) * AST]) + lcB;
        bLd[s] = (uint32_t)__cvta_generic_to_shared(&smem[s * STG_H + A_TILE + (wN + lr) * AST]) + lcB;
    }

    float acc[2][8][4];
#pragma unroll
    for (int i = 0; i < 2; i++)
#pragma unroll
        for (int j = 0; j < 8; j++)
#pragma unroll
            for (int r = 0; r < 4; r++) acc[i][j][r] = 0.f;

    const int KT = K / 32;

#define LOAD_STG(kt_, s_)                                                      \
    {                                                                          \
        const __half* ag_  = Ag  + (kt_) * 32;                                 \
        const __half* wg_  = Wg  + (kt_) * 32;                                 \
        const __half* wg2_ = Wg2 + (kt_) * 32;                                 \
        CP16(aSt[s_], ag_);                                                    \
        CP16(bSt[s_], wg_);                                                    \
        CP16(bSt2[s_], wg2_);                                                  \
    }

    // prologue: stages 0,1,2
    LOAD_STG(0, 0);
    asm volatile("cp.async.commit_group;\n");
    LOAD_STG(1, 1);
    asm volatile("cp.async.commit_group;\n");
    LOAD_STG(2, 2);
    asm volatile("cp.async.commit_group;\n");

    for (int kt = 0; kt < KT; kt++) {
        asm volatile("cp.async.wait_group 2;\n");
        __syncthreads();
        const int buf = kt % STGS;
        {
            const int pf = kt + 3;
            if (pf < KT) LOAD_STG(pf, pf % STGS);
            asm volatile("cp.async.commit_group;\n");
        }
#pragma unroll
        for (int kk = 0; kk < 2; kk++) {
            uint32_t af[2][4], bf[4][4];
#pragma unroll
            for (int mt = 0; mt < 2; mt++)
                ldsm4(af[mt][0], af[mt][1], af[mt][2], af[mt][3],
                      aLd[buf] + (mt * 16 * AST + kk * 16) * 2);
#pragma unroll
            for (int nt = 0; nt < 4; nt++)
                ldsm4(bf[nt][0], bf[nt][1], bf[nt][2], bf[nt][3],
                      bLd[buf] + (nt * 16 * AST + kk * 16) * 2);
#pragma unroll
            for (int mt = 0; mt < 2; mt++)
#pragma unroll
                for (int j = 0; j < 8; j++) {
                    uint32_t bb[2] = { bf[j >> 1][(j & 1)], bf[j >> 1][(j & 1) + 2] };
                    mma_f16(acc[mt][j], af[mt], bb);
                }
        }
    }

    // epilogue
    const int qr = lane >> 2, qc = lane & 3;
    float rw = 0.f;
    const int* idx = nullptr;
    const float* feat = nullptr;
    float* outz = nullptr;
    if (EPI == 2) {
        rw   = rw0[z];
        idx  = idx0 + (size_t)z * BATCH;
        feat = (z == 0) ? feat0 : feat1;
        outz = out0 + (long long)z * sOut;
    }
    __half* C = (EPI == 2) ? nullptr : (C0 + (size_t)z * sC);

#pragma unroll
    for (int mt = 0; mt < 2; mt++) {
        const int rm0 = m0 + wM + mt * 16 + qr;
#pragma unroll
        for (int r = 0; r < 2; r++) {
            const int gm = rm0 + r * 8;
            if (gm >= M) continue;
            int orow = 0;
            if (EPI == 2) orow = idx[gm];
#pragma unroll
            for (int j = 0; j < 8; j++) {
                const int gn = n0 + wN + j * 8 + qc * 2;
                float v0 = acc[mt][j][r * 2 + 0] + bias[gn];
                float v1 = acc[mt][j][r * 2 + 1] + bias[gn + 1];
                if (EPI == 0) {
                    reinterpret_cast<__half2*>(&C[(size_t)gm * N + gn])[0] =
                        __floats2half2_rn(v0, v1);
                } else if (EPI == 1) {
                    reinterpret_cast<__half2*>(&C[(size_t)gm * N + gn])[0] =
                        __floats2half2_rn(gelu_exact(v0), gelu_exact(v1));
                } else {
                    float2 t = *reinterpret_cast<const float2*>(&feat[(size_t)orow * HDIM + gn]);
                    *reinterpret_cast<float2*>(&outz[(size_t)orow * HDIM + gn]) =
                        make_float2(rw * t.x + (1.f - rw) * v0,
                                    rw * t.y + (1.f - rw) * v1);
                }
            }
        }
    }
#undef LOAD_STG
}

// ---------------------------------------------------------------------------
// Fused residual-add + LayerNorm (half in/out, fp32 math)
// ---------------------------------------------------------------------------
__global__ void ln_k(__half* __restrict__ x0, const __half* __restrict__ t0,
                     long long tsZ, const float* __restrict__ g0, long long gS,
                     const float* __restrict__ b0) {
    int z = blockIdx.y;
    int row = blockIdx.x;
    if (row >= d_cnt[z]) return;
    __half* x = x0 + (size_t)z * BH + (size_t)row * HDIM;
    const __half* t = t0 + (size_t)z * tsZ + (size_t)row * HDIM;
    const float* g  = g0 + (size_t)z * gS;
    const float* bb = b0 + (size_t)z * gS;
    int tid = threadIdx.x;
    uint2 ux = reinterpret_cast<const uint2*>(x)[tid];
    uint2 ut = reinterpret_cast<const uint2*>(t)[tid];
    float2 x0f = __half22float2(*reinterpret_cast<__half2*>(&ux.x));
    float2 x1f = __half22float2(*reinterpret_cast<__half2*>(&ux.y));
    float2 t0f = __half22float2(*reinterpret_cast<__half2*>(&ut.x));
    float2 t1f = __half22float2(*reinterpret_cast<__half2*>(&ut.y));
    float v0 = x0f.x + t0f.x, v1 = x0f.y + t0f.y;
    float v2 = x1f.x + t1f.x, v3 = x1f.y + t1f.y;
    float s = v0 + v1 + v2 + v3;
    float q = v0 * v0 + v1 * v1 + v2 * v2 + v3 * v3;
#pragma unroll
    for (int o = 16; o; o >>= 1) {
        s += __shfl_xor_sync(0xffffffffu, s, o);
        q += __shfl_xor_sync(0xffffffffu, q, o);
    }
    __shared__ float ss[4], sq[4];
    int w = tid >> 5, lane = tid & 31;
    if (lane == 0) { ss[w] = s; sq[w] = q; }
    __syncthreads();
    s = ss[0] + ss[1] + ss[2] + ss[3];
    q = sq[0] + sq[1] + sq[2] + sq[3];
    float mean = s * (1.f / HDIM);
    float var  = q * (1.f / HDIM) - mean * mean;
    float inv  = rsqrtf(var + LN_EPS);
    float4 gv = reinterpret_cast<const float4*>(g)[tid];
    float4 bv = reinterpret_cast<const float4*>(bb)[tid];
    uint2 uo;
    *reinterpret_cast<__half2*>(&uo.x) = __floats2half2_rn((v0 - mean) * inv * gv.x + bv.x,
                                                           (v1 - mean) * inv * gv.y + bv.y);
    *reinterpret_cast<__half2*>(&uo.y) = __floats2half2_rn((v2 - mean) * inv * gv.z + bv.z,
                                                           (v3 - mean) * inv * gv.w + bv.w);
    reinterpret_cast<uint2*>(x)[tid] = uo;
}

// ---------------------------------------------------------------------------
// Host launch
// ---------------------------------------------------------------------------
extern "C" void kernel_launch(void* const* d_in, const int* in_sizes, int n_in,
                              void* d_out, int out_size) {
    const float* img  = (const float*)d_in[0];
    const float* txt  = (const float*)d_in[1];
    const float* ipw  = (const float*)d_in[2];
    const float* ipb  = (const float*)d_in[3];
    const float* qkvw = (const float*)d_in[4];
    const float* qkvb = (const float*)d_in[5];
    const float* aow  = (const float*)d_in[6];
    const float* aob  = (const float*)d_in[7];
    const float* ln1g = (const float*)d_in[8];
    const float* ln1b = (const float*)d_in[9];
    const float* ln2g = (const float*)d_in[10];
    const float* ln2b = (const float*)d_in[11];
    const float* f1w  = (const float*)d_in[12];
    const float* f1b  = (const float*)d_in[13];
    const float* f2w  = (const float*)d_in[14];
    const float* f2b  = (const float*)d_in[15];
    const float* opw  = (const float*)d_in[16];
    const float* opb  = (const float*)d_in[17];
    const float* rw   = (const float*)d_in[18];
    const float* pw1  = (const float*)d_in[19];
    const float* pb1  = (const float*)d_in[20];
    const float* pw2  = (const float*)d_in[21];
    const float* pb2  = (const float*)d_in[22];
    const float* emb  = (const float*)d_in[23];
    const int*   mt   = (const int*)d_in[24];
    float* out = (float*)d_out;

    __half *pSrc, *pTgt, *pX, *pT, *pAttn, *pHH;
    __half *pWip, *pWao, *pWwvT, *pWcombo, *pWf1, *pWf2, *pWop;
    float *pBcombo, *pZeros;
    int *pIdx;
    cudaGetSymbolAddress((void**)&pSrc,    h_src);
    cudaGetSymbolAddress((void**)&pTgt,    h_tgt);
    cudaGetSymbolAddress((void**)&pX,      h_x);
    cudaGetSymbolAddress((void**)&pT,      h_t);
    cudaGetSymbolAddress((void**)&pAttn,   h_attn);
    cudaGetSymbolAddress((void**)&pHH,     h_hh);
    cudaGetSymbolAddress((void**)&pWip,    w_ip);
    cudaGetSymbolAddress((void**)&pWao,    w_ao);
    cudaGetSymbolAddress((void**)&pWwvT,   w_wvT);
    cudaGetSymbolAddress((void**)&pWcombo, w_combo);
    cudaGetSymbolAddress((void**)&pWf1,    w_f1);
    cudaGetSymbolAddress((void**)&pWf2,    w_f2);
    cudaGetSymbolAddress((void**)&pWop,    w_op);
    cudaGetSymbolAddress((void**)&pBcombo, d_bcombo);
    cudaGetSymbolAddress((void**)&pZeros,  d_zeros);
    cudaGetSymbolAddress((void**)&pIdx,    d_idx);

    cudaFuncSetAttribute(gemm_h<0>, cudaFuncAttributeMaxDynamicSharedMemorySize, SMEM_BYTES);
    cudaFuncSetAttribute(gemm_h<1>, cudaFuncAttributeMaxDynamicSharedMemorySize, SMEM_BYTES);
    cudaFuncSetAttribute(gemm_h<2>, cudaFuncAttributeMaxDynamicSharedMemorySize, SMEM_BYTES);

    dim3 g4 (BATCH / 128, HDIM / 256, 2);   // (128, 2, 2)
    dim3 g16(BATCH / 128, FF / 256,   2);   // (128, 8, 2)
    dim3 g6 (BATCH / 128, HDIM / 256, 6);   // (128, 2, 6)
    dim3 gC (HDIM / 128,  HDIM / 256, 6);   // (4, 2, 6) combo fold

    const int CVT_TOT = (int)(2 * (2 * HH / 4) + (6 * HH / 4) + 2 * (6ULL * FF * HDIM / 4));

    reset_k<<<1, 32>>>();
    compact_k<<<BATCH / 256, 256>>>(mt);
    cvt_wv_k<<<(int)(6 * HH / 4 + 255) / 256, 256>>>(qkvw);
    cvt_all_k<<<(CVT_TOT + 255) / 256, 256>>>(ipw, aow, f1w, f2w, opw);
    transp_k<<<dim3(16, 16, 6), dim3(32, 8)>>>();
    // combo[z][n][i] = sum_o ao[z][n][o] * wv[z][o][i]  (M=512 fixed)
    gemm_h<0><<<gC, 512, SMEM_BYTES>>>(pWao, (long long)HH, 0, 3,
                           pWwvT, (long long)HH, pZeros, 0,
                           HDIM, HDIM, pWcombo, (long long)HH,
                           nullptr, nullptr, nullptr, nullptr, nullptr, 0, HDIM);
    bcombo_k<<<6 * HDIM, 32>>>(aow, qkvb, aob);
    gather_k<<<dim3(BATCH * HDIM / 4 / 256, 2), 256>>>(img, txt);

    // attn[z] = tgt[gi] @ combo[z]^T + b_combo[z]
    gemm_h<0><<<g6, 512, SMEM_BYTES>>>(pTgt, (long long)BH, 1, 3,
                           pWcombo, (long long)HH, pBcombo, HDIM,
                           HDIM, HDIM, pAttn, (long long)BH,
                           nullptr, nullptr, nullptr, nullptr, nullptr, 0, 0);
    // x = src @ ipw^T + ipb
    gemm_h<0><<<g4, 512, SMEM_BYTES>>>(pSrc, (long long)BH, 1, 1,
                           pWip, (long long)HH, ipb, HDIM,
                           HDIM, HDIM, pX, (long long)BH,
                           nullptr, nullptr, nullptr, nullptr, nullptr, 0, 0);

    prior1_k<<<2 * HDIM / 4, 128>>>(emb, pw1, pb1);
    prior2_k<<<2 * HDIM / 4, 128>>>(pw2, pb2);
    base_k<<<BATCH * HDIM / 4 / 256, 256>>>(img, txt, mt, out);

    for (int l = 0; l < NLAYER; l++) {
        ln_k<<<dim3(BATCH, 2), 128>>>(pX, pAttn + (size_t)l * BH, (long long)(3 * BH),
                                      ln1g + l * HDIM, (long long)(NLAYER * HDIM),
                                      ln1b + l * HDIM);
        gemm_h<1><<<g16, 512, SMEM_BYTES>>>(pX, (long long)BH, 1, 1,
                                pWf1 + (size_t)l * FF * HDIM, (long long)(3ULL * FF * HDIM),
                                f1b + l * FF, (long long)(NLAYER * FF),
                                HDIM, FF, pHH, (long long)BFF,
                                nullptr, nullptr, nullptr, nullptr, nullptr, 0, 0);
        gemm_h<0><<<g4, 512, SMEM_BYTES>>>(pHH, (long long)BFF, 1, 1,
                               pWf2 + (size_t)l * HDIM * FF, (long long)(3ULL * HDIM * FF),
                               f2b + l * HDIM, (long long)(NLAYER * HDIM),
                               FF, HDIM, pT, (long long)BH,
                               nullptr, nullptr, nullptr, nullptr, nullptr, 0, 0);
        ln_k<<<dim3(BATCH, 2), 128>>>(pX, pT, (long long)BH,
                                      ln2g + l * HDIM, (long long)(NLAYER * HDIM),
                                      ln2b + l * HDIM);
    }

    // out[idx[m]] = rw*feat + (1-rw)*(x @ opw^T + opb)
    gemm_h<2><<<g4, 512, SMEM_BYTES>>>(pX, (long long)BH, 1, 1,
                           pWop, (long long)HH, opb, HDIM,
                           HDIM, HDIM, nullptr, 0,
                           pIdx, txt, img, rw,
                           out + BH, -(long long)BH, 0);
}

// round 14
// speedup vs baseline: 1.2073x; 1.0648x over previous
#include <cuda_runtime.h>
#include <cuda_fp16.h>
#include <math.h>
#include <stdint.h>

#define HDIM 512
#define NLAYER 3
#define BATCH 16384
#define LN_EPS 1e-5f
#define FF 2048
#define BH ((size_t)BATCH * HDIM)
#define BFF ((size_t)BATCH * FF)
#define HH ((size_t)HDIM * HDIM)

// ---------------------------------------------------------------------------
// Scratch (device globals)
// ---------------------------------------------------------------------------
__device__ __half h_src [2 * BATCH * HDIM];
__device__ __half h_tgt [2 * BATCH * HDIM];
__device__ __half h_x   [2 * BATCH * HDIM];
__device__ __half h_t   [2 * BATCH * HDIM];
__device__ __half h_attn[6 * BATCH * HDIM];
__device__ __half h_hh  [2ULL * BATCH * FF];
__device__ __half w_ip[2 * HDIM * HDIM];
__device__ __half w_wvT[6 * HDIM * HDIM];
__device__ __half w_ao[6 * HDIM * HDIM];
__device__ __half w_combo[6 * HDIM * HDIM];
__device__ __half w_f1[6 * FF * HDIM];
__device__ __half w_f2[6 * HDIM * FF];
__device__ __half w_op[2 * HDIM * HDIM];
__device__ float d_bcombo[6 * HDIM];
__device__ float d_zeros[HDIM];            // zero-initialized
__device__ int   d_idx[2 * BATCH];
__device__ int   d_pos[BATCH];             // row -> compacted slot
__device__ int   d_cnt[2];
__device__ float d_prior_h[2 * HDIM];
__device__ float d_prior  [2 * HDIM];

__device__ __forceinline__ float gelu_exact(float v) {
    return 0.5f * v * (1.0f + erff(v * 0.70710678118654752440f));
}

#define CP16(dst, src) \
    asm volatile("cp.async.cg.shared.global [%0], [%1], 16;\n" :: "r"(dst), "l"(src))

__device__ __forceinline__ void ldsm4(uint32_t& r0, uint32_t& r1, uint32_t& r2,
                                      uint32_t& r3, uint32_t addr) {
    asm volatile("ldmatrix.sync.aligned.m8n8.x4.shared.b16 {%0,%1,%2,%3}, [%4];"
                 : "=r"(r0), "=r"(r1), "=r"(r2), "=r"(r3) : "r"(addr));
}

__device__ __forceinline__ void mma_f16(float* c, const uint32_t* a, const uint32_t* b) {
    asm volatile(
        "mma.sync.aligned.m16n8k16.row.col.f32.f16.f16.f32 "
        "{%0,%1,%2,%3}, {%4,%5,%6,%7}, {%8,%9}, {%0,%1,%2,%3};\n"
        : "+f"(c[0]), "+f"(c[1]), "+f"(c[2]), "+f"(c[3])
        : "r"(a[0]), "r"(a[1]), "r"(a[2]), "r"(a[3]), "r"(b[0]), "r"(b[1]));
}

// ---------------------------------------------------------------------------
// Small kernels
// ---------------------------------------------------------------------------
__global__ void reset_k() { if (threadIdx.x < 2) d_cnt[threadIdx.x] = 0; }

__global__ void compact_k(const int* __restrict__ mt) {
    int i = blockIdx.x * 256 + threadIdx.x;
    if (i < BATCH) {
        int m = mt[i];
        if (m == 1) {
            int p = atomicAdd(&d_cnt[0], 1);
            d_idx[p] = i;  d_pos[i] = p;
        } else if (m == 2) {
            int p = atomicAdd(&d_cnt[1], 1);
            d_idx[BATCH + p] = i;  d_pos[i] = p;
        }
    }
}

// 4 warps per block, one output per warp
__global__ void prior1_k(const float* __restrict__ emb, const float* __restrict__ w1,
                         const float* __restrict__ b1) {
    int j = blockIdx.x * 4 + (threadIdx.x >> 5);
    int lane = threadIdx.x & 31;
    const float* wr = w1 + (size_t)j * HDIM;
    float s = 0.f;
    for (int k = lane; k < HDIM; k += 32) s += emb[k] * wr[k];
#pragma unroll
    for (int o = 16; o; o >>= 1) s += __shfl_xor_sync(0xffffffffu, s, o);
    if (lane == 0) d_prior_h[j] = gelu_exact(s + b1[j]);
}

__global__ void prior2_k(const float* __restrict__ w2, const float* __restrict__ b2) {
    int j = blockIdx.x * 4 + (threadIdx.x >> 5);
    int lane = threadIdx.x & 31;
    const float* wr = w2 + (size_t)j * (2 * HDIM);
    float s = 0.f;
    for (int k = lane; k < 2 * HDIM; k += 32) s += d_prior_h[k] * wr[k];
#pragma unroll
    for (int o = 16; o; o >>= 1) s += __shfl_xor_sync(0xffffffffu, s, o);
    if (lane == 0) d_prior[j] = s + b2[j];
}

// merged base output + compacted gather (one pass over img/txt)
__global__ void basegather_k(const float* __restrict__ img, const float* __restrict__ txt,
                             const int* __restrict__ mt, float* __restrict__ out) {
    int i = blockIdx.x * 256 + threadIdx.x;      // over B*H/4 float4
    const int TOT = BATCH * HDIM / 4;
    if (i >= TOT) return;
    int b = i >> 7, h4 = i & 127, m = mt[b];
    float4 iv = reinterpret_cast<const float4*>(img)[i];
    float4 tv = reinterpret_cast<const float4*>(txt)[i];
    float4 ov = iv, ow = tv;
    if (m == 3) {
        ov = reinterpret_cast<const float4*>(d_prior)[h4];
        ow = reinterpret_cast<const float4*>(d_prior + HDIM)[h4];
    }
    reinterpret_cast<float4*>(out)[i]       = ov;
    reinterpret_cast<float4*>(out)[TOT + i] = ow;
    if (m == 1 || m == 2) {
        int z = m - 1;
        int p = d_pos[b];
        // z=0: src=img,tgt=txt ; z=1: src=txt,tgt=img
        float4 sv = (z == 0) ? iv : tv;
        float4 gv = (z == 0) ? tv : iv;
        size_t off2 = (size_t)z * BH / 2 + ((size_t)p * 128 + h4) * 2;
        reinterpret_cast<__half2*>(h_src)[off2]     = __floats2half2_rn(sv.x, sv.y);
        reinterpret_cast<__half2*>(h_src)[off2 + 1] = __floats2half2_rn(sv.z, sv.w);
        reinterpret_cast<__half2*>(h_tgt)[off2]     = __floats2half2_rn(gv.x, gv.y);
        reinterpret_cast<__half2*>(h_tgt)[off2 + 1] = __floats2half2_rn(gv.z, gv.w);
    }
}

// one launch converting all plain-layout weights
__global__ void cvt_all_k(const float* __restrict__ ipw, const float* __restrict__ aow,
                          const float* __restrict__ f1w, const float* __restrict__ f2w,
                          const float* __restrict__ opw) {
    const int N_IP = (int)(2 * HH / 4);            // 131072
    const int N_AO = (int)(6 * HH / 4);            // 393216
    const int N_FF = (int)(6ULL * FF * HDIM / 4);  // 1572864
    int i = blockIdx.x * 256 + threadIdx.x;
    const float* s; __half* d; int li;
    if (i < N_IP)                          { s = ipw; d = w_ip; li = i; }
    else if ((i -= N_IP) < N_AO)           { s = aow; d = w_ao; li = i; }
    else if ((i -= N_AO) < N_FF)           { s = f1w; d = w_f1; li = i; }
    else if ((i -= N_FF) < N_FF)           { s = f2w; d = w_f2; li = i; }
    else if ((i -= N_FF) < N_IP)           { s = opw; d = w_op; li = i; }
    else return;
    float4 v = reinterpret_cast<const float4*>(s)[li];
    reinterpret_cast<__half2*>(d)[2 * li + 0] = __floats2half2_rn(v.x, v.y);
    reinterpret_cast<__half2*>(d)[2 * li + 1] = __floats2half2_rn(v.z, v.w);
}

// fused convert + transpose: qkvw wv-slice [z][o][i] (fp32) -> w_wvT [z][i][o] (half)
__global__ void cvtT_wv_k(const float* __restrict__ qkvw) {
    __shared__ __half tile[32][33];
    int z  = blockIdx.z;
    int o0 = blockIdx.x * 32;
    int i0 = blockIdx.y * 32;
    const float* src = qkvw + (size_t)z * 3 * HH + 2 * HH;
    __half* dst = w_wvT + (size_t)z * HH;
    int tx = threadIdx.x, ty0 = threadIdx.y;      // 32 x 8
#pragma unroll
    for (int dy = 0; dy < 32; dy += 8)
        tile[ty0 + dy][tx] = __float2half_rn(src[(size_t)(o0 + ty0 + dy) * HDIM + i0 + tx]);
    __syncthreads();
#pragma unroll
    for (int dy = 0; dy < 32; dy += 8)
        dst[(size_t)(i0 + ty0 + dy) * HDIM + o0 + tx] = tile[tx][ty0 + dy];
}

// b_combo[z][n] = sum_o ao[z][n][o] * bv[z][o] + ao_b[z][n]   (fp32)
__global__ void bcombo_k(const float* __restrict__ aow, const float* __restrict__ qkvb,
                         const float* __restrict__ aob) {
    int z = blockIdx.x >> 9;
    int n = blockIdx.x & 511;
    int lane = threadIdx.x;
    const float* ar = aow + ((size_t)z * HDIM + n) * HDIM;
    const float* bv = qkvb + (size_t)z * 3 * HDIM + 2 * HDIM;
    float s = 0.f;
    for (int o = lane; o < HDIM; o += 32) s += ar[o] * bv[o];
#pragma unroll
    for (int o = 16; o; o >>= 1) s += __shfl_xor_sync(0xffffffffu, s, o);
    if (lane == 0) d_bcombo[z * HDIM + n] = s + aob[(size_t)z * HDIM + n];
}

// ---------------------------------------------------------------------------
// fp16 mma.sync GEMM: C[m,n] = sum_k A[m,k]*W[n,k] (+epilogue)
// BM=128, BN=256, BK=32, 4-stage cp.async, 512 threads (R11 config).
// ---------------------------------------------------------------------------
#define AST 40
#define STGS 4
#define A_TILE (128 * AST)
#define B_TILE (256 * AST)
#define STG_H (A_TILE + B_TILE)
#define SMEM_BYTES (STGS * STG_H * 2)     // 122880 B

template <int EPI>
__global__ __launch_bounds__(512, 1)
void gemm_h(const __half* __restrict__ A0, long long sA, int aByGi, int mDiv,
            const __half* __restrict__ W0, long long sW,
            const float* __restrict__ B0, long long sB,
            int K, int N,
            __half* __restrict__ C0, long long sC,
            const int* __restrict__ idx0,
            const float* __restrict__ feat0, const float* __restrict__ feat1,
            const float* __restrict__ rw0,
            float* __restrict__ out0, long long sOut, int fixedM) {
    const int z  = blockIdx.z;
    const int gi = z / mDiv;
    const int M  = fixedM > 0 ? fixedM : d_cnt[gi];
    const int m0 = blockIdx.x * 128;
    if (m0 >= M) return;
    const int n0 = blockIdx.y * 256;

    const __half* A    = A0 + (size_t)(aByGi ? gi : z) * sA;
    const __half* W    = W0 + (size_t)z * sW;
    const float*  bias = B0 + (size_t)z * sB;

    extern __shared__ __align__(16) __half smem[];

    const int tid  = threadIdx.x;
    const int warp = tid >> 5;
    const int lane = tid & 31;
    const int wM = (warp >> 2) * 32;
    const int wN = (warp & 3) * 64;

    const int grow = tid >> 2;
    const int gcol = (tid & 3) * 8;
    const __half* Ag  = A + (size_t)(m0 + grow) * K + gcol;
    const __half* Wg  = W + (size_t)(n0 + grow) * K + gcol;
    const __half* Wg2 = Wg + (size_t)128 * K;

    uint32_t aSt[STGS], bSt[STGS], bSt2[STGS];
#pragma unroll
    for (int s = 0; s < STGS; s++) {
        aSt[s]  = (uint32_t)__cvta_generic_to_shared(&smem[s * STG_H + grow * AST + gcol]);
        bSt[s]  = (uint32_t)__cvta_generic_to_shared(&smem[s * STG_H + A_TILE + grow * AST + gcol]);
        bSt2[s] = bSt[s] + 128 * AST * 2;
    }

    const int lr  = ((lane >> 3) & 1) * 8 + (lane & 7);
    const int lcB = (lane >> 4) * 16;
    uint32_t aLd[STGS], bLd[STGS];
#pragma unroll
    for (int s = 0; s < STGS; s++) {
        aLd[s] = (uint32_t)__cvta_generic_to_shared(&smem[s * STG_H + (wM + lr) * AST]) + lcB;
        bLd[s] = (uint32_t)__cvta_generic_to_shared(&smem[s * STG_H + A_TILE + (wN + lr) * AST]) + lcB;
    }

    float acc[2][8][4];
#pragma unroll
    for (int i = 0; i < 2; i++)
#pragma unroll
        for (int j = 0; j < 8; j++)
#pragma unroll
            for (int r = 0; r < 4; r++) acc[i][j][r] = 0.f;

    const int KT = K / 32;

#define LOAD_STG(kt_, s_)                                                      \
    {                                                                          \
        const __half* ag_  = Ag  + (kt_) * 32;                                 \
        const __half* wg_  = Wg  + (kt_) * 32;                                 \
        const __half* wg2_ = Wg2 + (kt_) * 32;                                 \
        CP16(aSt[s_], ag_);                                                    \
        CP16(bSt[s_], wg_);                                                    \
        CP16(bSt2[s_], wg2_);                                                  \
    }

    LOAD_STG(0, 0);
    asm volatile("cp.async.commit_group;\n");
    LOAD_STG(1, 1);
    asm volatile("cp.async.commit_group;\n");
    LOAD_STG(2, 2);
    asm volatile("cp.async.commit_group;\n");

    for (int kt = 0; kt < KT; kt++) {
        asm volatile("cp.async.wait_group 2;\n");
        __syncthreads();
        const int buf = kt % STGS;
        {
            const int pf = kt + 3;
            if (pf < KT) LOAD_STG(pf, pf % STGS);
            asm volatile("cp.async.commit_group;\n");
        }
#pragma unroll
        for (int kk = 0; kk < 2; kk++) {
            uint32_t af[2][4], bf[4][4];
#pragma unroll
            for (int mt = 0; mt < 2; mt++)
                ldsm4(af[mt][0], af[mt][1], af[mt][2], af[mt][3],
                      aLd[buf] + (mt * 16 * AST + kk * 16) * 2);
#pragma unroll
            for (int nt = 0; nt < 4; nt++)
                ldsm4(bf[nt][0], bf[nt][1], bf[nt][2], bf[nt][3],
                      bLd[buf] + (nt * 16 * AST + kk * 16) * 2);
#pragma unroll
            for (int mt = 0; mt < 2; mt++)
#pragma unroll
                for (int j = 0; j < 8; j++) {
                    uint32_t bb[2] = { bf[j >> 1][(j & 1)], bf[j >> 1][(j & 1) + 2] };
                    mma_f16(acc[mt][j], af[mt], bb);
                }
        }
    }

    // epilogue
    const int qr = lane >> 2, qc = lane & 3;
    float rw = 0.f;
    const int* idx = nullptr;
    const float* feat = nullptr;
    float* outz = nullptr;
    if (EPI == 2) {
        rw   = rw0[z];
        idx  = idx0 + (size_t)z * BATCH;
        feat = (z == 0) ? feat0 : feat1;
        outz = out0 + (long long)z * sOut;
    }
    __half* C = (EPI == 2) ? nullptr : (C0 + (size_t)z * sC);

#pragma unroll
    for (int mt = 0; mt < 2; mt++) {
        const int rm0 = m0 + wM + mt * 16 + qr;
#pragma unroll
        for (int r = 0; r < 2; r++) {
            const int gm = rm0 + r * 8;
            if (gm >= M) continue;
            int orow = 0;
            if (EPI == 2) orow = idx[gm];
#pragma unroll
            for (int j = 0; j < 8; j++) {
                const int gn = n0 + wN + j * 8 + qc * 2;
                float v0 = acc[mt][j][r * 2 + 0] + bias[gn];
                float v1 = acc[mt][j][r * 2 + 1] + bias[gn + 1];
                if (EPI == 0) {
                    reinterpret_cast<__half2*>(&C[(size_t)gm * N + gn])[0] =
                        __floats2half2_rn(v0, v1);
                } else if (EPI == 1) {
                    reinterpret_cast<__half2*>(&C[(size_t)gm * N + gn])[0] =
                        __floats2half2_rn(gelu_exact(v0), gelu_exact(v1));
                } else {
                    float2 t = *reinterpret_cast<const float2*>(&feat[(size_t)orow * HDIM + gn]);
                    *reinterpret_cast<float2*>(&outz[(size_t)orow * HDIM + gn]) =
                        make_float2(rw * t.x + (1.f - rw) * v0,
                                    rw * t.y + (1.f - rw) * v1);
                }
            }
        }
    }
#undef LOAD_STG
}

// ---------------------------------------------------------------------------
// Fused residual-add + LayerNorm, warp-per-row (no smem, no block sync):
//   x = LN(x + t) * g + b.  16 halves per lane. 8 rows per 256-thread block.
// ---------------------------------------------------------------------------
__global__ void ln_k(__half* __restrict__ x0, const __half* __restrict__ t0,
                     long long tsZ, const float* __restrict__ g0, long long gS,
                     const float* __restrict__ b0) {
    int z = blockIdx.y;
    int row = blockIdx.x * 8 + (threadIdx.x >> 5);
    if (row >= d_cnt[z]) return;
    int lane = threadIdx.x & 31;
    __half* x = x0 + (size_t)z * BH + (size_t)row * HDIM + lane * 16;
    const __half* t = t0 + (size_t)z * tsZ + (size_t)row * HDIM + lane * 16;
    const float* g  = g0 + (size_t)z * gS + lane * 16;
    const float* bb = b0 + (size_t)z * gS + lane * 16;

    uint4 ux0 = reinterpret_cast<const uint4*>(x)[0];
    uint4 ux1 = reinterpret_cast<const uint4*>(x)[1];
    uint4 ut0 = reinterpret_cast<const uint4*>(t)[0];
    uint4 ut1 = reinterpret_cast<const uint4*>(t)[1];

    float v[16];
    {
        const uint32_t* px = reinterpret_cast<const uint32_t*>(&ux0);
        const uint32_t* pt = reinterpret_cast<const uint32_t*>(&ut0);
#pragma unroll
        for (int i = 0; i < 4; i++) {
            float2 a = __half22float2(*reinterpret_cast<const __half2*>(&px[i]));
            float2 c = __half22float2(*reinterpret_cast<const __half2*>(&pt[i]));
            v[2 * i]     = a.x + c.x;
            v[2 * i + 1] = a.y + c.y;
        }
        px = reinterpret_cast<const uint32_t*>(&ux1);
        pt = reinterpret_cast<const uint32_t*>(&ut1);
#pragma unroll
        for (int i = 0; i < 4; i++) {
            float2 a = __half22float2(*reinterpret_cast<const __half2*>(&px[i]));
            float2 c = __half22float2(*reinterpret_cast<const __half2*>(&pt[i]));
            v[8 + 2 * i]     = a.x + c.x;
            v[8 + 2 * i + 1] = a.y + c.y;
        }
    }

    float s = 0.f, q = 0.f;
#pragma unroll
    for (int i = 0; i < 16; i++) { s += v[i]; q += v[i] * v[i]; }
#pragma unroll
    for (int o = 16; o; o >>= 1) {
        s += __shfl_xor_sync(0xffffffffu, s, o);
        q += __shfl_xor_sync(0xffffffffu, q, o);
    }
    float mean = s * (1.f / HDIM);
    float var  = q * (1.f / HDIM) - mean * mean;
    float inv  = rsqrtf(var + LN_EPS);

    uint4 o0, o1;
    uint32_t* po = reinterpret_cast<uint32_t*>(&o0);
#pragma unroll
    for (int i = 0; i < 4; i++) {
        float2 gv = *reinterpret_cast<const float2*>(&g[2 * i]);
        float2 bv = *reinterpret_cast<const float2*>(&bb[2 * i]);
        *reinterpret_cast<__half2*>(&po[i]) =
            __floats2half2_rn((v[2 * i]     - mean) * inv * gv.x + bv.x,
                              (v[2 * i + 1] - mean) * inv * gv.y + bv.y);
    }
    po = reinterpret_cast<uint32_t*>(&o1);
#pragma unroll
    for (int i = 0; i < 4; i++) {
        float2 gv = *reinterpret_cast<const float2*>(&g[8 + 2 * i]);
        float2 bv = *reinterpret_cast<const float2*>(&bb[8 + 2 * i]);
        *reinterpret_cast<__half2*>(&po[i]) =
            __floats2half2_rn((v[8 + 2 * i]     - mean) * inv * gv.x + bv.x,
                              (v[8 + 2 * i + 1] - mean) * inv * gv.y + bv.y);
    }
    reinterpret_cast<uint4*>(x)[0] = o0;
    reinterpret_cast<uint4*>(x)[1] = o1;
}

// ---------------------------------------------------------------------------
// Host launch
// ---------------------------------------------------------------------------
extern "C" void kernel_launch(void* const* d_in, const int* in_sizes, int n_in,
                              void* d_out, int out_size) {
    const float* img  = (const float*)d_in[0];
    const float* txt  = (const float*)d_in[1];
    const float* ipw  = (const float*)d_in[2];
    const float* ipb  = (const float*)d_in[3];
    const float* qkvw = (const float*)d_in[4];
    const float* qkvb = (const float*)d_in[5];
    const float* aow  = (const float*)d_in[6];
    const float* aob  = (const float*)d_in[7];
    const float* ln1g = (const float*)d_in[8];
    const float* ln1b = (const float*)d_in[9];
    const float* ln2g = (const float*)d_in[10];
    const float* ln2b = (const float*)d_in[11];
    const float* f1w  = (const float*)d_in[12];
    const float* f1b  = (const float*)d_in[13];
    const float* f2w  = (const float*)d_in[14];
    const float* f2b  = (const float*)d_in[15];
    const float* opw  = (const float*)d_in[16];
    const float* opb  = (const float*)d_in[17];
    const float* rw   = (const float*)d_in[18];
    const float* pw1  = (const float*)d_in[19];
    const float* pb1  = (const float*)d_in[20];
    const float* pw2  = (const float*)d_in[21];
    const float* pb2  = (const float*)d_in[22];
    const float* emb  = (const float*)d_in[23];
    const int*   mt   = (const int*)d_in[24];
    float* out = (float*)d_out;

    __half *pSrc, *pTgt, *pX, *pT, *pAttn, *pHH;
    __half *pWip, *pWao, *pWwvT, *pWcombo, *pWf1, *pWf2, *pWop;
    float *pBcombo, *pZeros;
    int *pIdx;
    cudaGetSymbolAddress((void**)&pSrc,    h_src);
    cudaGetSymbolAddress((void**)&pTgt,    h_tgt);
    cudaGetSymbolAddress((void**)&pX,      h_x);
    cudaGetSymbolAddress((void**)&pT,      h_t);
    cudaGetSymbolAddress((void**)&pAttn,   h_attn);
    cudaGetSymbolAddress((void**)&pHH,     h_hh);
    cudaGetSymbolAddress((void**)&pWip,    w_ip);
    cudaGetSymbolAddress((void**)&pWao,    w_ao);
    cudaGetSymbolAddress((void**)&pWwvT,   w_wvT);
    cudaGetSymbolAddress((void**)&pWcombo, w_combo);
    cudaGetSymbolAddress((void**)&pWf1,    w_f1);
    cudaGetSymbolAddress((void**)&pWf2,    w_f2);
    cudaGetSymbolAddress((void**)&pWop,    w_op);
    cudaGetSymbolAddress((void**)&pBcombo, d_bcombo);
    cudaGetSymbolAddress((void**)&pZeros,  d_zeros);
    cudaGetSymbolAddress((void**)&pIdx,    d_idx);

    cudaFuncSetAttribute(gemm_h<0>, cudaFuncAttributeMaxDynamicSharedMemorySize, SMEM_BYTES);
    cudaFuncSetAttribute(gemm_h<1>, cudaFuncAttributeMaxDynamicSharedMemorySize, SMEM_BYTES);
    cudaFuncSetAttribute(gemm_h<2>, cudaFuncAttributeMaxDynamicSharedMemorySize, SMEM_BYTES);

    dim3 g4 (BATCH / 128, HDIM / 256, 2);
    dim3 g16(BATCH / 128, FF / 256,   2);
    dim3 g6 (BATCH / 128, HDIM / 256, 6);
    dim3 gC (HDIM / 128,  HDIM / 256, 6);
    dim3 gLN(BATCH / 8, 2);

    const int CVT_TOT = (int)(2 * (2 * HH / 4) + (6 * HH / 4) + 2 * (6ULL * FF * HDIM / 4));

    reset_k<<<1, 32>>>();
    compact_k<<<BATCH / 256, 256>>>(mt);
    cvtT_wv_k<<<dim3(16, 16, 6), dim3(32, 8)>>>(qkvw);
    cvt_all_k<<<(CVT_TOT + 255) / 256, 256>>>(ipw, aow, f1w, f2w, opw);
    // combo[z][n][i] = sum_o ao[z][n][o] * wv[z][o][i]  (M=512 fixed)
    gemm_h<0><<<gC, 512, SMEM_BYTES>>>(pWao, (long long)HH, 0, 3,
                           pWwvT, (long long)HH, pZeros, 0,
                           HDIM, HDIM, pWcombo, (long long)HH,
                           nullptr, nullptr, nullptr, nullptr, nullptr, 0, HDIM);
    bcombo_k<<<6 * HDIM, 32>>>(aow, qkvb, aob);
    prior1_k<<<2 * HDIM / 4, 128>>>(emb, pw1, pb1);
    prior2_k<<<2 * HDIM / 4, 128>>>(pw2, pb2);
    basegather_k<<<BATCH * HDIM / 4 / 256, 256>>>(img, txt, mt, out);

    // attn[z] = tgt[gi] @ combo[z]^T + b_combo[z]
    gemm_h<0><<<g6, 512, SMEM_BYTES>>>(pTgt, (long long)BH, 1, 3,
                           pWcombo, (long long)HH, pBcombo, HDIM,
                           HDIM, HDIM, pAttn, (long long)BH,
                           nullptr, nullptr, nullptr, nullptr, nullptr, 0, 0);
    // x = src @ ipw^T + ipb
    gemm_h<0><<<g4, 512, SMEM_BYTES>>>(pSrc, (long long)BH, 1, 1,
                           pWip, (long long)HH, ipb, HDIM,
                           HDIM, HDIM, pX, (long long)BH,
                           nullptr, nullptr, nullptr, nullptr, nullptr, 0, 0);

    for (int l = 0; l < NLAYER; l++) {
        ln_k<<<gLN, 256>>>(pX, pAttn + (size_t)l * BH, (long long)(3 * BH),
                           ln1g + l * HDIM, (long long)(NLAYER * HDIM),
                           ln1b + l * HDIM);
        gemm_h<1><<<g16, 512, SMEM_BYTES>>>(pX, (long long)BH, 1, 1,
                                pWf1 + (size_t)l * FF * HDIM, (long long)(3ULL * FF * HDIM),
                                f1b + l * FF, (long long)(NLAYER * FF),
                                HDIM, FF, pHH, (long long)BFF,
                                nullptr, nullptr, nullptr, nullptr, nullptr, 0, 0);
        gemm_h<0><<<g4, 512, SMEM_BYTES>>>(pHH, (long long)BFF, 1, 1,
                               pWf2 + (size_t)l * HDIM * FF, (long long)(3ULL * HDIM * FF),
                               f2b + l * HDIM, (long long)(NLAYER * HDIM),
                               FF, HDIM, pT, (long long)BH,
                               nullptr, nullptr, nullptr, nullptr, nullptr, 0, 0);
        ln_k<<<gLN, 256>>>(pX, pT, (long long)BH,
                           ln2g + l * HDIM, (long long)(NLAYER * HDIM),
                           ln2b + l * HDIM);
    }

    // out[idx[m]] = rw*feat + (1-rw)*(x @ opw^T + opb)
    gemm_h<2><<<g4, 512, SMEM_BYTES>>>(pX, (long long)BH, 1, 1,
                           pWop, (long long)HH, opb, HDIM,
                           HDIM, HDIM, nullptr, 0,
                           pIdx, txt, img, rw,
                           out + BH, -(long long)BH, 0);
}